// round 4
// baseline (speedup 1.0000x reference)
#include <cuda_runtime.h>
#include <cuda_bf16.h>
#include <stdint.h>

// ============================================================================
// Problem constants
// ============================================================================
#define NROWS 8192
#define DIMK  256
#define NLBL  1024
#define NSPLIT 2                       // column splits
#define COLS_PER_CTA (NROWS / NSPLIT)  // 4096
#define TTILES (COLS_PER_CTA / 128)    // 32
#define TEMP_INV 14.285714285714286f   // 1/0.07
// exp((d-1)/T) = 2^(d*K - K), K = (1/T)*log2(e)
#define K_EX2 20.609929191666664f

// ============================================================================
// Device scratch (no allocation allowed)
// ============================================================================
__device__ __align__(128) __nv_bfloat16 g_en[NROWS * DIMK];  // normalized rows, bf16
__device__ int   g_lbl[NROWS];
__device__ int   g_hist[NLBL];
__device__ int   g_is64;
__device__ float g_S[4 * NSPLIT][NROWS];  // partial exp-sums per (split, warpN)
__device__ float g_P[4 * NSPLIT][NROWS];  // partial positive-sim sums

// ============================================================================
// PTX helpers (baseline sm_80+ only — target is compute_103 WITHOUT 'a')
// ============================================================================
__device__ __forceinline__ uint32_t smem_u32(const void* p) {
    uint32_t a;
    asm("{ .reg .u64 t; cvta.to.shared.u64 t, %1; cvt.u32.u64 %0, t; }" : "=r"(a) : "l"(p));
    return a;
}

__device__ __forceinline__ void cp16(uint32_t dst, const void* src) {
    asm volatile("cp.async.cg.shared.global [%0], [%1], 16;" :: "r"(dst), "l"(src));
}
#define CP_COMMIT() asm volatile("cp.async.commit_group;" ::: "memory")
#define CP_WAIT1()  asm volatile("cp.async.wait_group 1;" ::: "memory")
#define CP_WAIT0()  asm volatile("cp.async.wait_group 0;" ::: "memory")

__device__ __forceinline__ void ldsm4(uint32_t* r, uint32_t addr) {
    asm volatile("ldmatrix.sync.aligned.m8n8.x4.shared.b16 {%0,%1,%2,%3}, [%4];"
        : "=r"(r[0]), "=r"(r[1]), "=r"(r[2]), "=r"(r[3]) : "r"(addr));
}

__device__ __forceinline__ void mma16816(float* d, const uint32_t* a, const uint32_t* b) {
    asm volatile(
        "mma.sync.aligned.m16n8k16.row.col.f32.bf16.bf16.f32 "
        "{%0,%1,%2,%3}, {%4,%5,%6,%7}, {%8,%9}, {%0,%1,%2,%3};"
        : "+f"(d[0]), "+f"(d[1]), "+f"(d[2]), "+f"(d[3])
        : "r"(a[0]), "r"(a[1]), "r"(a[2]), "r"(a[3]), "r"(b[0]), "r"(b[1]));
}

__device__ __forceinline__ float ex2f(float x) {
    float e;
    asm("ex2.approx.f32 %0, %1;" : "=f"(e) : "f"(x));
    return e;
}

// ============================================================================
// SMEM layout (padded K-major tiles: 128 rows x 264 bf16 -> 528 B row stride)
// ============================================================================
#define ROWB   528
#define TILEB  (128 * ROWB)                // 67584
#define SOFF_A   0
#define SOFF_B0  TILEB
#define SOFF_B1  (2 * TILEB)
#define SMEM_TOTAL (3 * TILEB)             // 202752

// Fill one 128-row x 256-col bf16 tile via cp.async. 256 threads, 4096 chunks.
__device__ __forceinline__ void load_tile(uint32_t dst_base, int grow_base, int tid) {
    #pragma unroll
    for (int i = 0; i < 16; i++) {
        int c = tid + i * 256;     // 0..4095
        int r = c >> 5;            // row
        int q = c & 31;            // 16B chunk
        cp16(dst_base + r * ROWB + q * 16,
             (const void*)(g_en + (size_t)(grow_base + r) * DIMK + q * 8));
    }
}

// ============================================================================
// Kernel 1: zero histogram + detect labels dtype (merged)
// ============================================================================
__global__ void init_kernel(const int* lab32) {
    int tid = threadIdx.x;  // 1024
    if (tid < NLBL) g_hist[tid] = 0;
    __shared__ int any;
    if (tid == 0) any = 0;
    __syncthreads();
    for (int i = tid; i < 4096; i += 1024)
        if (lab32[2 * i + 1] != 0) any = 1;  // benign race
    __syncthreads();
    if (tid == 0) g_is64 = (any == 0) ? 1 : 0;
}

// ============================================================================
// Kernel 2: normalize rows -> bf16 (warp per row), labels -> int32, histogram
// ============================================================================
__global__ void prep_kernel(const float* __restrict__ emb, const void* __restrict__ labels) {
    int warp = threadIdx.x >> 5, lane = threadIdx.x & 31;
    int row = blockIdx.x * 8 + warp;
    const float4* src = (const float4*)(emb + (size_t)row * DIMK);
    float4 v0 = __ldg(src + lane);
    float4 v1 = __ldg(src + lane + 32);
    float ss = v0.x * v0.x + v0.y * v0.y + v0.z * v0.z + v0.w * v0.w
             + v1.x * v1.x + v1.y * v1.y + v1.z * v1.z + v1.w * v1.w;
    #pragma unroll
    for (int o = 16; o; o >>= 1) ss += __shfl_xor_sync(0xffffffffu, ss, o);
    float inv = 1.0f / fmaxf(sqrtf(ss), 1e-12f);
    __nv_bfloat16* dst = g_en + (size_t)row * DIMK;
    __nv_bfloat162* d2 = (__nv_bfloat162*)dst;
    d2[2 * lane + 0]  = __nv_bfloat162(__float2bfloat16(v0.x * inv), __float2bfloat16(v0.y * inv));
    d2[2 * lane + 1]  = __nv_bfloat162(__float2bfloat16(v0.z * inv), __float2bfloat16(v0.w * inv));
    d2[64 + 2 * lane] = __nv_bfloat162(__float2bfloat16(v1.x * inv), __float2bfloat16(v1.y * inv));
    d2[65 + 2 * lane] = __nv_bfloat162(__float2bfloat16(v1.z * inv), __float2bfloat16(v1.w * inv));
    if (lane == 0) {
        int l = g_is64 ? (int)((const long long*)labels)[row] : ((const int*)labels)[row];
        g_lbl[row] = l;
        atomicAdd(&g_hist[l], 1);
    }
}

// ============================================================================
// Kernel 3: fused bf16 mma.sync GEMM.
// 256 threads = 8 warps, warp grid 2M x 4N, warp tile 64x32.
// Epilogue of tile t-1 interleaved into MMA loop of tile t.
// ============================================================================
typedef float Acc[4][4][4];  // [mf (16-row frag)][j (8-col)][r]

template <bool HAS_PREV>
__device__ __forceinline__ void do_tile(
    int t, uint32_t sb, int tid, int lid, int warpN,
    int split_base, int row_base,
    uint32_t aAddr, uint32_t bOff,
    Acc& cur, Acc& prev,
    float* Sa, float* Pa, const int* myl, const int* rowg,
    int* lpx, int* lpy, int& prev_tb, int& prev_dt)
{
    uint32_t bufB = sb + ((t & 1) ? SOFF_B1 : SOFF_B0);
    // prefetch next tile's B into the other buffer (freed by prior tile-end barrier)
    if (t + 1 < TTILES) {
        uint32_t nbuf = sb + (((t + 1) & 1) ? SOFF_B1 : SOFF_B0);
        load_tile(nbuf, split_base + (t + 1) * 128, tid);
        CP_COMMIT();
        CP_WAIT1();
    } else {
        CP_WAIT0();
    }
    __syncthreads();  // B(t) visible to all warps

    #pragma unroll
    for (int mf = 0; mf < 4; mf++)
        #pragma unroll
        for (int j = 0; j < 4; j++)
            #pragma unroll
            for (int r = 0; r < 4; r++) cur[mf][j][r] = 0.f;

    int coff = warpN * 32 + 2 * (lid & 3);  // column base within tile (j*8 added below)
    uint32_t bAddr = bufB + bOff;

    #pragma unroll
    for (int ks = 0; ks < 16; ks++) {
        uint32_t a[4][4], b[2][4];
        ldsm4(a[0], aAddr + ks * 32);
        ldsm4(a[1], aAddr + 16 * ROWB + ks * 32);
        ldsm4(a[2], aAddr + 32 * ROWB + ks * 32);
        ldsm4(a[3], aAddr + 48 * ROWB + ks * 32);
        ldsm4(b[0], bAddr + ks * 32);
        ldsm4(b[1], bAddr + 16 * ROWB + ks * 32);
        #pragma unroll
        for (int mf = 0; mf < 4; mf++)
            #pragma unroll
            for (int jj = 0; jj < 2; jj++) {
                mma16816(cur[mf][2 * jj + 0], a[mf], &b[jj][0]);
                mma16816(cur[mf][2 * jj + 1], a[mf], &b[jj][2]);
            }
        if (HAS_PREV) {
            // interleaved epilogue: 4 values of previous tile's acc per ks step
            #pragma unroll
            for (int u = 0; u < 4; u++) {
                const int v = 4 * ks + u;
                const int mf = v >> 4, j = (v >> 2) & 3, r = v & 3;
                const int hi = r >> 1, lo = r & 1;
                const int idx = mf * 2 + hi;
                float d = prev[mf][j][r];
                Sa[idx] += ex2f(fmaf(d, K_EX2, -K_EX2));
                int lj = lo ? lpy[j] : lpx[j];
                int cg = prev_tb + coff + j * 8 + lo;
                bool m = (lj == myl[idx]) && (!prev_dt || cg != rowg[idx]);
                if (m) Pa[idx] += d;
            }
        }
    }

    // stage this tile's column labels for its epilogue (next iteration)
    int tb = split_base + t * 128;
    #pragma unroll
    for (int j = 0; j < 4; j++) {
        int2 lp = __ldg((const int2*)(g_lbl + tb + warpN * 32 + j * 8 + 2 * (lid & 3)));
        lpx[j] = lp.x;
        lpy[j] = lp.y;
    }
    prev_tb = tb;
    prev_dt = (tb == row_base);

    __syncthreads();  // all warps done reading both buffers for this tile
}

__global__ void __launch_bounds__(256, 1) gemm_kernel() {
    extern __shared__ char smem[];
    uint32_t sb = smem_u32(smem);
    int tid = threadIdx.x, wid = tid >> 5, lid = tid & 31;
    int warpM = wid & 1, warpN = wid >> 1;  // 2M x 4N grid, 64x32 warp tiles
    int split = blockIdx.x, rtile = blockIdx.y;
    int row_base = rtile * 128;
    int split_base = split * COLS_PER_CTA;

    // per-lane fixed rows: row_base + warpM*64 + mf*16 + hi*8 + lid/4
    int rowg[8], myl[8];
    #pragma unroll
    for (int idx = 0; idx < 8; idx++) {
        int mf = idx >> 1, hi = idx & 1;
        rowg[idx] = row_base + warpM * 64 + mf * 16 + hi * 8 + (lid >> 2);
        myl[idx] = __ldg(&g_lbl[rowg[idx]]);
    }

    // ldmatrix per-lane base addresses
    uint32_t aAddr = sb + SOFF_A
        + (uint32_t)(warpM * 64 + (lid & 7) + ((lid >> 3) & 1) * 8) * ROWB
        + ((lid >> 4) & 1) * 16;
    uint32_t bOff =
        (uint32_t)(warpN * 32 + (lid & 7) + ((lid >> 4) & 1) * 8) * ROWB
        + ((lid >> 3) & 1) * 16;

    // Prologue: A tile + B tile 0 as one cp.async group
    load_tile(sb + SOFF_A, row_base, tid);
    load_tile(sb + SOFF_B0, split_base, tid);
    CP_COMMIT();

    Acc acc0, acc1;
    float Sa[8] = {0.f, 0.f, 0.f, 0.f, 0.f, 0.f, 0.f, 0.f};
    float Pa[8] = {0.f, 0.f, 0.f, 0.f, 0.f, 0.f, 0.f, 0.f};
    int lpx[4], lpy[4];
    int prev_tb = 0, prev_dt = 0;

    do_tile<false>(0, sb, tid, lid, warpN, split_base, row_base, aAddr, bOff,
                   acc0, acc1, Sa, Pa, myl, rowg, lpx, lpy, prev_tb, prev_dt);
    for (int tt = 0; tt < 15; tt++) {
        do_tile<true>(1 + 2 * tt, sb, tid, lid, warpN, split_base, row_base, aAddr, bOff,
                      acc1, acc0, Sa, Pa, myl, rowg, lpx, lpy, prev_tb, prev_dt);
        do_tile<true>(2 + 2 * tt, sb, tid, lid, warpN, split_base, row_base, aAddr, bOff,
                      acc0, acc1, Sa, Pa, myl, rowg, lpx, lpy, prev_tb, prev_dt);
    }
    do_tile<true>(31, sb, tid, lid, warpN, split_base, row_base, aAddr, bOff,
                  acc1, acc0, Sa, Pa, myl, rowg, lpx, lpy, prev_tb, prev_dt);

    // tail epilogue for tile 31 (acc1), labels in lpx/lpy, tb/dt in prev_*
    {
        int coff = warpN * 32 + 2 * (lid & 3);
        #pragma unroll
        for (int v = 0; v < 64; v++) {
            const int mf = v >> 4, j = (v >> 2) & 3, r = v & 3;
            const int hi = r >> 1, lo = r & 1;
            const int idx = mf * 2 + hi;
            float d = acc1[mf][j][r];
            Sa[idx] += ex2f(fmaf(d, K_EX2, -K_EX2));
            int lj = lo ? lpy[j] : lpx[j];
            int cg = prev_tb + coff + j * 8 + lo;
            bool m = (lj == myl[idx]) && (!prev_dt || cg != rowg[idx]);
            if (m) Pa[idx] += d;
        }
    }

    // quad reduction (lanes lid&3 share rows, cover columns) and store
    int slot = split * 4 + warpN;
    #pragma unroll
    for (int idx = 0; idx < 8; idx++) {
        float s = Sa[idx], p = Pa[idx];
        s += __shfl_xor_sync(0xffffffffu, s, 1);
        s += __shfl_xor_sync(0xffffffffu, s, 2);
        p += __shfl_xor_sync(0xffffffffu, p, 1);
        p += __shfl_xor_sync(0xffffffffu, p, 2);
        if ((lid & 3) == 0) {
            g_S[slot][rowg[idx]] = s;
            g_P[slot][rowg[idx]] = p;
        }
    }
}

// ============================================================================
// Kernel 4: final reduction -> scalar mean loss
// ============================================================================
__global__ void finalize_kernel(float* __restrict__ out) {
    int tid = threadIdx.x;  // 1024 threads
    float acc = 0.f;
    for (int i = tid; i < NROWS; i += 1024) {
        float S = 0.f, P = 0.f;
        #pragma unroll
        for (int s = 0; s < 4 * NSPLIT; s++) {
            S += g_S[s][i];
            P += g_P[s][i];
        }
        int cnt = g_hist[g_lbl[i]] - 1;
        if (cnt > 0)
            acc += TEMP_INV + logf(S) - (P * TEMP_INV) / (float)cnt;
    }
    #pragma unroll
    for (int o = 16; o; o >>= 1) acc += __shfl_xor_sync(0xffffffffu, acc, o);
    __shared__ float ws[32];
    if ((tid & 31) == 0) ws[tid >> 5] = acc;
    __syncthreads();
    if (tid < 32) {
        float v = ws[tid];
        #pragma unroll
        for (int o = 16; o; o >>= 1) v += __shfl_xor_sync(0xffffffffu, v, o);
        if (tid == 0) out[0] = v / (float)NROWS;
    }
}

// ============================================================================
// Launch
// ============================================================================
extern "C" void kernel_launch(void* const* d_in, const int* in_sizes, int n_in,
                              void* d_out, int out_size) {
    const float* emb;
    const void* lab;
    if (in_sizes[0] == NROWS * DIMK) {
        emb = (const float*)d_in[0];
        lab = d_in[1];
    } else {
        emb = (const float*)d_in[1];
        lab = d_in[0];
    }

    cudaFuncSetAttribute(gemm_kernel, cudaFuncAttributeMaxDynamicSharedMemorySize, SMEM_TOTAL);

    init_kernel<<<1, 1024>>>((const int*)lab);
    prep_kernel<<<NROWS / 8, 256>>>(emb, lab);
    gemm_kernel<<<dim3(NSPLIT, 64), 256, SMEM_TOTAL>>>();
    finalize_kernel<<<1, 1024>>>((float*)d_out);
}

// round 5
// speedup vs baseline: 1.2314x; 1.2314x over previous
#include <cuda_runtime.h>
#include <cuda_bf16.h>
#include <stdint.h>

// ============================================================================
// Problem constants
// ============================================================================
#define NROWS 8192
#define DIMK  256
#define NLBL  1024
#define NSPLIT 2                       // column splits
#define COLS_PER_CTA (NROWS / NSPLIT)  // 4096
#define TTILES (COLS_PER_CTA / 128)    // 32
#define TEMP_INV 14.285714285714286f   // 1/0.07
// exp((d-1)/T) = 2^(d*K - K), K = (1/T)*log2(e)
#define K_EX2 20.609929191666664f

// ============================================================================
// Device scratch (no allocation allowed)
// ============================================================================
__device__ __align__(128) __nv_bfloat16 g_en[NROWS * DIMK];  // normalized rows, bf16
__device__ int   g_lbl[NROWS];
__device__ int   g_hist[NLBL];
__device__ int   g_is64;
__device__ float g_S[4 * NSPLIT][NROWS];  // partial exp-sums per (split, warpN)
__device__ float g_P[4 * NSPLIT][NROWS];  // partial positive-sim sums
__device__ float g_pb[8];                 // per-block partial losses
__device__ int   g_done;                  // finalize completion counter

// ============================================================================
// PTX helpers (baseline sm_80+ only — target is compute_103 WITHOUT 'a')
// ============================================================================
__device__ __forceinline__ uint32_t smem_u32(const void* p) {
    uint32_t a;
    asm("{ .reg .u64 t; cvta.to.shared.u64 t, %1; cvt.u32.u64 %0, t; }" : "=r"(a) : "l"(p));
    return a;
}

__device__ __forceinline__ void cp16(uint32_t dst, const void* src) {
    asm volatile("cp.async.cg.shared.global [%0], [%1], 16;" :: "r"(dst), "l"(src));
}
#define CP_COMMIT() asm volatile("cp.async.commit_group;" ::: "memory")
#define CP_WAIT0()  asm volatile("cp.async.wait_group 0;" ::: "memory")

__device__ __forceinline__ void ldsm4(uint32_t* r, uint32_t addr) {
    asm volatile("ldmatrix.sync.aligned.m8n8.x4.shared.b16 {%0,%1,%2,%3}, [%4];"
        : "=r"(r[0]), "=r"(r[1]), "=r"(r[2]), "=r"(r[3]) : "r"(addr));
}

__device__ __forceinline__ void mma16816(float* d, const uint32_t* a, const uint32_t* b) {
    asm volatile(
        "mma.sync.aligned.m16n8k16.row.col.f32.bf16.bf16.f32 "
        "{%0,%1,%2,%3}, {%4,%5,%6,%7}, {%8,%9}, {%0,%1,%2,%3};"
        : "+f"(d[0]), "+f"(d[1]), "+f"(d[2]), "+f"(d[3])
        : "r"(a[0]), "r"(a[1]), "r"(a[2]), "r"(a[3]), "r"(b[0]), "r"(b[1]));
}

__device__ __forceinline__ float ex2f(float x) {
    float e;
    asm("ex2.approx.f32 %0, %1;" : "=f"(e) : "f"(x));
    return e;
}

// ============================================================================
// SMEM layout (padded K-major tiles: 128 rows x 264 bf16 -> 528 B row stride)
// ============================================================================
#define ROWB   528
#define TILEB  (128 * ROWB)                // 67584
#define SOFF_A   0
#define SOFF_B0  TILEB
#define SOFF_B1  (2 * TILEB)
#define SMEM_TOTAL (3 * TILEB)             // 202752

// Fill one 128-row x 256-col bf16 tile via cp.async. 512 threads, 4096 chunks.
__device__ __forceinline__ void load_tile(uint32_t dst_base, int grow_base, int tid) {
    #pragma unroll
    for (int i = 0; i < 8; i++) {
        int c = tid + i * 512;     // 0..4095
        int r = c >> 5;            // row
        int q = c & 31;            // 16B chunk
        cp16(dst_base + r * ROWB + q * 16,
             (const void*)(g_en + (size_t)(grow_base + r) * DIMK + q * 8));
    }
}

// ============================================================================
// Kernel 1: zero histogram + reset finalize counter + detect labels dtype
// ============================================================================
__global__ void init_kernel(const int* lab32) {
    int tid = threadIdx.x;  // 1024
    if (tid < NLBL) g_hist[tid] = 0;
    if (tid == 0) g_done = 0;
    __shared__ int any;
    if (tid == 0) any = 0;
    __syncthreads();
    for (int i = tid; i < 4096; i += 1024)
        if (lab32[2 * i + 1] != 0) any = 1;  // benign race
    __syncthreads();
    if (tid == 0) g_is64 = (any == 0) ? 1 : 0;
}

// ============================================================================
// Kernel 2: normalize rows -> bf16 (warp per row), labels -> int32, histogram
// ============================================================================
__global__ void prep_kernel(const float* __restrict__ emb, const void* __restrict__ labels) {
    int warp = threadIdx.x >> 5, lane = threadIdx.x & 31;
    int row = blockIdx.x * 8 + warp;
    const float4* src = (const float4*)(emb + (size_t)row * DIMK);
    float4 v0 = __ldg(src + lane);
    float4 v1 = __ldg(src + lane + 32);
    float ss = v0.x * v0.x + v0.y * v0.y + v0.z * v0.z + v0.w * v0.w
             + v1.x * v1.x + v1.y * v1.y + v1.z * v1.z + v1.w * v1.w;
    #pragma unroll
    for (int o = 16; o; o >>= 1) ss += __shfl_xor_sync(0xffffffffu, ss, o);
    float inv = 1.0f / fmaxf(sqrtf(ss), 1e-12f);
    __nv_bfloat162* d2 = (__nv_bfloat162*)(g_en + (size_t)row * DIMK);
    d2[2 * lane + 0]  = __nv_bfloat162(__float2bfloat16(v0.x * inv), __float2bfloat16(v0.y * inv));
    d2[2 * lane + 1]  = __nv_bfloat162(__float2bfloat16(v0.z * inv), __float2bfloat16(v0.w * inv));
    d2[64 + 2 * lane] = __nv_bfloat162(__float2bfloat16(v1.x * inv), __float2bfloat16(v1.y * inv));
    d2[65 + 2 * lane] = __nv_bfloat162(__float2bfloat16(v1.z * inv), __float2bfloat16(v1.w * inv));
    if (lane == 0) {
        int l = g_is64 ? (int)((const long long*)labels)[row] : ((const int*)labels)[row];
        g_lbl[row] = l;
        atomicAdd(&g_hist[l], 1);
    }
}

// ============================================================================
// Kernel 3: fused bf16 mma.sync GEMM, 512 threads = 16 warps (4M x 4N),
// warp tile 32x32. ONE barrier per tile; epilogue of tile t-1 interleaved
// into the MMA loop of tile t (MUFU rides on tensor/smem phase).
// ============================================================================
typedef float Acc[2][4][4];  // [mf][j][r]

template <bool HAS_PREV>
__device__ __forceinline__ void do_tile(
    int t, uint32_t sb, int tid, int lid, int warpN,
    int split_base, int row_base,
    uint32_t aAddr, uint32_t bOff,
    Acc& cur, Acc& prev,
    float* Sa, float* Pa, const int* myl, const int* rowg,
    int* lpx, int* lpy, int& prev_tb, int& prev_dt)
{
    // B(t) arrival (only one group can be pending) + all warps done with B(t-1)
    CP_WAIT0();
    __syncthreads();

    // prefetch B(t+1) into buffer (t+1)&1 — freed by the barrier above
    if (t + 1 < TTILES) {
        uint32_t nbuf = sb + (((t + 1) & 1) ? SOFF_B1 : SOFF_B0);
        load_tile(nbuf, split_base + (t + 1) * 128, tid);
        CP_COMMIT();
    }

    #pragma unroll
    for (int mf = 0; mf < 2; mf++)
        #pragma unroll
        for (int j = 0; j < 4; j++)
            #pragma unroll
            for (int r = 0; r < 4; r++) cur[mf][j][r] = 0.f;

    int coff = warpN * 32 + 2 * (lid & 3);  // column offset base (j*8 added below)
    uint32_t bAddr = sb + ((t & 1) ? SOFF_B1 : SOFF_B0) + bOff;

    #pragma unroll
    for (int ks = 0; ks < 16; ks++) {
        uint32_t a[2][4], b[2][4];
        ldsm4(a[0], aAddr + ks * 32);
        ldsm4(a[1], aAddr + 16 * ROWB + ks * 32);
        ldsm4(b[0], bAddr + ks * 32);
        ldsm4(b[1], bAddr + 16 * ROWB + ks * 32);
        #pragma unroll
        for (int mf = 0; mf < 2; mf++)
            #pragma unroll
            for (int jj = 0; jj < 2; jj++) {
                mma16816(cur[mf][2 * jj + 0], a[mf], &b[jj][0]);
                mma16816(cur[mf][2 * jj + 1], a[mf], &b[jj][2]);
            }
        if (HAS_PREV) {
            // interleaved epilogue: 2 values of previous tile's acc per ks step
            #pragma unroll
            for (int u = 0; u < 2; u++) {
                const int v = 2 * ks + u;
                const int mf = v >> 4, j = (v >> 2) & 3, r = v & 3;
                const int hi = r >> 1, lo = r & 1;
                const int idx = mf * 2 + hi;
                float d = prev[mf][j][r];
                Sa[idx] += ex2f(fmaf(d, K_EX2, -K_EX2));
                int lj = lo ? lpy[j] : lpx[j];
                int cg = prev_tb + coff + j * 8 + lo;
                bool m = (lj == myl[idx]) && (!prev_dt || cg != rowg[idx]);
                if (m) Pa[idx] += d;
            }
        }
    }

    // stage this tile's column labels for its epilogue (next iteration)
    int tb = split_base + t * 128;
    #pragma unroll
    for (int j = 0; j < 4; j++) {
        int2 lp = __ldg((const int2*)(g_lbl + tb + warpN * 32 + j * 8 + 2 * (lid & 3)));
        lpx[j] = lp.x;
        lpy[j] = lp.y;
    }
    prev_tb = tb;
    prev_dt = (tb == row_base);
}

__global__ void __launch_bounds__(512, 1) gemm_kernel() {
    extern __shared__ char smem[];
    uint32_t sb = smem_u32(smem);
    int tid = threadIdx.x, wid = tid >> 5, lid = tid & 31;
    int warpM = wid & 3, warpN = wid >> 2;  // 4 x 4 warp grid, 32x32 warp tiles
    int split = blockIdx.x, rtile = blockIdx.y;
    int row_base = rtile * 128;
    int split_base = split * COLS_PER_CTA;

    // per-lane fixed rows: row_base + warpM*32 + mf*16 + hi*8 + lid/4
    int rowg[4], myl[4];
    #pragma unroll
    for (int idx = 0; idx < 4; idx++) {
        int mf = idx >> 1, hi = idx & 1;
        rowg[idx] = row_base + warpM * 32 + mf * 16 + hi * 8 + (lid >> 2);
        myl[idx] = __ldg(&g_lbl[rowg[idx]]);
    }

    // ldmatrix per-lane base addresses
    uint32_t aAddr = sb + SOFF_A
        + (uint32_t)(warpM * 32 + (lid & 7) + ((lid >> 3) & 1) * 8) * ROWB
        + ((lid >> 4) & 1) * 16;
    uint32_t bOff =
        (uint32_t)(warpN * 32 + (lid & 7) + ((lid >> 4) & 1) * 8) * ROWB
        + ((lid >> 3) & 1) * 16;

    // Prologue: A tile + B tile 0 as one cp.async group
    load_tile(sb + SOFF_A, row_base, tid);
    load_tile(sb + SOFF_B0, split_base, tid);
    CP_COMMIT();

    Acc acc0, acc1;
    float Sa[4] = {0.f, 0.f, 0.f, 0.f};
    float Pa[4] = {0.f, 0.f, 0.f, 0.f};
    int lpx[4], lpy[4];
    int prev_tb = 0, prev_dt = 0;

    do_tile<false>(0, sb, tid, lid, warpN, split_base, row_base, aAddr, bOff,
                   acc0, acc1, Sa, Pa, myl, rowg, lpx, lpy, prev_tb, prev_dt);
    for (int tt = 0; tt < 15; tt++) {
        do_tile<true>(1 + 2 * tt, sb, tid, lid, warpN, split_base, row_base, aAddr, bOff,
                      acc1, acc0, Sa, Pa, myl, rowg, lpx, lpy, prev_tb, prev_dt);
        do_tile<true>(2 + 2 * tt, sb, tid, lid, warpN, split_base, row_base, aAddr, bOff,
                      acc0, acc1, Sa, Pa, myl, rowg, lpx, lpy, prev_tb, prev_dt);
    }
    do_tile<true>(31, sb, tid, lid, warpN, split_base, row_base, aAddr, bOff,
                  acc1, acc0, Sa, Pa, myl, rowg, lpx, lpy, prev_tb, prev_dt);

    // tail epilogue for tile 31 (acc1), labels in lpx/lpy, tb/dt in prev_*
    {
        int coff = warpN * 32 + 2 * (lid & 3);
        #pragma unroll
        for (int v = 0; v < 32; v++) {
            const int mf = v >> 4, j = (v >> 2) & 3, r = v & 3;
            const int hi = r >> 1, lo = r & 1;
            const int idx = mf * 2 + hi;
            float d = acc1[mf][j][r];
            Sa[idx] += ex2f(fmaf(d, K_EX2, -K_EX2));
            int lj = lo ? lpy[j] : lpx[j];
            int cg = prev_tb + coff + j * 8 + lo;
            bool m = (lj == myl[idx]) && (!prev_dt || cg != rowg[idx]);
            if (m) Pa[idx] += d;
        }
    }

    // quad reduction (lanes lid&3 share rows, cover columns) and store
    int slot = split * 4 + warpN;
    #pragma unroll
    for (int idx = 0; idx < 4; idx++) {
        float s = Sa[idx], p = Pa[idx];
        s += __shfl_xor_sync(0xffffffffu, s, 1);
        s += __shfl_xor_sync(0xffffffffu, s, 2);
        p += __shfl_xor_sync(0xffffffffu, p, 1);
        p += __shfl_xor_sync(0xffffffffu, p, 2);
        if ((lid & 3) == 0) {
            g_S[slot][rowg[idx]] = s;
            g_P[slot][rowg[idx]] = p;
        }
    }
}

// ============================================================================
// Kernel 4: final reduction -> scalar mean loss. 8 blocks x 1024 threads,
// one row per thread; deterministic partials + last-block-done combine.
// ============================================================================
__global__ void finalize_kernel(float* __restrict__ out) {
    int tid = threadIdx.x;
    int i = blockIdx.x * 1024 + tid;  // one row per thread
    float S = 0.f, P = 0.f;
    #pragma unroll
    for (int s = 0; s < 4 * NSPLIT; s++) {
        S += g_S[s][i];
        P += g_P[s][i];
    }
    int cnt = g_hist[g_lbl[i]] - 1;
    float acc = (cnt > 0) ? (TEMP_INV + __logf(S) - (P * TEMP_INV) / (float)cnt) : 0.f;

    #pragma unroll
    for (int o = 16; o; o >>= 1) acc += __shfl_xor_sync(0xffffffffu, acc, o);
    __shared__ float ws[32];
    if ((tid & 31) == 0) ws[tid >> 5] = acc;
    __syncthreads();
    if (tid < 32) {
        float v = ws[tid];
        #pragma unroll
        for (int o = 16; o; o >>= 1) v += __shfl_xor_sync(0xffffffffu, v, o);
        if (tid == 0) {
            g_pb[blockIdx.x] = v;
            __threadfence();
            int prev = atomicAdd(&g_done, 1);
            if (prev == 7) {  // last block: fixed-order combine (deterministic)
                float tot = 0.f;
                #pragma unroll
                for (int b = 0; b < 8; b++) tot += ((volatile float*)g_pb)[b];
                out[0] = tot / (float)NROWS;
            }
        }
    }
}

// ============================================================================
// Launch
// ============================================================================
extern "C" void kernel_launch(void* const* d_in, const int* in_sizes, int n_in,
                              void* d_out, int out_size) {
    const float* emb;
    const void* lab;
    if (in_sizes[0] == NROWS * DIMK) {
        emb = (const float*)d_in[0];
        lab = d_in[1];
    } else {
        emb = (const float*)d_in[1];
        lab = d_in[0];
    }

    cudaFuncSetAttribute(gemm_kernel, cudaFuncAttributeMaxDynamicSharedMemorySize, SMEM_TOTAL);

    init_kernel<<<1, 1024>>>((const int*)lab);
    prep_kernel<<<NROWS / 8, 256>>>(emb, lab);
    gemm_kernel<<<dim3(NSPLIT, 64), 512, SMEM_TOTAL>>>();
    finalize_kernel<<<8, 1024>>>((float*)d_out);
}

// round 6
// speedup vs baseline: 1.4131x; 1.1476x over previous
#include <cuda_runtime.h>
#include <cuda_bf16.h>
#include <stdint.h>

// ============================================================================
// Problem constants
// ============================================================================
#define NROWS 8192
#define DIMK  256
#define NLBL  1024
#define NJOBS 4096                     // 64 row-tiles x 64 col-tiles of 128x128
#define TEMP_INV 14.285714285714286f   // 1/0.07
// exp((d-1)/T) = 2^(d*K - K), K = (1/T)*log2(e)
#define K_EX2 20.609929191666664f
#define MAXCTA 256

// ============================================================================
// Device scratch (no allocation allowed; zero-initialized)
// ============================================================================
__device__ __align__(128) __nv_bfloat16 g_en[NROWS * DIMK];  // normalized rows, bf16
__device__ int   g_lbl[NROWS];
__device__ int   g_hist[NLBL];
__device__ int   g_is64;
__device__ float g_diag[NROWS];               // self-dot of bf16 row (fp32)
__device__ float g_S2[MAXCTA][4][128];        // per-(CTA, segment) exp-sum partials
__device__ float g_P2[MAXCTA][4][128];        // per-(CTA, segment) positive-sum partials
__device__ int   g_seg_r[MAXCTA][4];          // rtile id of each segment
__device__ float g_pb[8];                     // per-block partial losses
__device__ int   g_done;                      // finalize completion counter

// ============================================================================
// PTX helpers (baseline sm_80+ only — target is compute_103 WITHOUT 'a')
// ============================================================================
__device__ __forceinline__ uint32_t smem_u32(const void* p) {
    uint32_t a;
    asm("{ .reg .u64 t; cvta.to.shared.u64 t, %1; cvt.u32.u64 %0, t; }" : "=r"(a) : "l"(p));
    return a;
}

__device__ __forceinline__ void cp16(uint32_t dst, const void* src) {
    asm volatile("cp.async.cg.shared.global [%0], [%1], 16;" :: "r"(dst), "l"(src));
}
#define CP_COMMIT() asm volatile("cp.async.commit_group;" ::: "memory")
#define CP_WAIT0()  asm volatile("cp.async.wait_group 0;" ::: "memory")

__device__ __forceinline__ void ldsm4(uint32_t* r, uint32_t addr) {
    asm volatile("ldmatrix.sync.aligned.m8n8.x4.shared.b16 {%0,%1,%2,%3}, [%4];"
        : "=r"(r[0]), "=r"(r[1]), "=r"(r[2]), "=r"(r[3]) : "r"(addr));
}

__device__ __forceinline__ void mma16816(float* d, const uint32_t* a, const uint32_t* b) {
    asm volatile(
        "mma.sync.aligned.m16n8k16.row.col.f32.bf16.bf16.f32 "
        "{%0,%1,%2,%3}, {%4,%5,%6,%7}, {%8,%9}, {%0,%1,%2,%3};"
        : "+f"(d[0]), "+f"(d[1]), "+f"(d[2]), "+f"(d[3])
        : "r"(a[0]), "r"(a[1]), "r"(a[2]), "r"(a[3]), "r"(b[0]), "r"(b[1]));
}

__device__ __forceinline__ float ex2f(float x) {
    float e;
    asm("ex2.approx.f32 %0, %1;" : "=f"(e) : "f"(x));
    return e;
}

// ============================================================================
// SMEM layout (padded K-major tiles: 128 rows x 264 bf16 -> 528 B row stride)
// ============================================================================
#define ROWB   528
#define TILEB  (128 * ROWB)                // 67584
#define SOFF_A   0
#define SOFF_B0  TILEB
#define SOFF_RED (3 * TILEB)               // 8 x 512B reduce buffers
#define SMEM_TOTAL (SOFF_RED + 4096)       // 206848

// Fill one 128-row x 256-col bf16 tile via cp.async. 512 threads, 4096 chunks.
__device__ __forceinline__ void load_tile(uint32_t dst_base, int grow_base, int tid) {
    #pragma unroll
    for (int i = 0; i < 8; i++) {
        int c = tid + i * 512;     // 0..4095
        int r = c >> 5;            // row
        int q = c & 31;            // 16B chunk
        cp16(dst_base + r * ROWB + q * 16,
             (const void*)(g_en + (size_t)(grow_base + r) * DIMK + q * 8));
    }
}

// ============================================================================
// Kernel 1: zero histogram + reset finalize counter + detect labels dtype
// ============================================================================
__global__ void init_kernel(const int* lab32) {
    int tid = threadIdx.x;  // 1024
    if (tid < NLBL) g_hist[tid] = 0;
    if (tid == 0) g_done = 0;
    __shared__ int any;
    if (tid == 0) any = 0;
    __syncthreads();
    for (int i = tid; i < 4096; i += 1024)
        if (lab32[2 * i + 1] != 0) any = 1;  // benign race
    __syncthreads();
    if (tid == 0) g_is64 = (any == 0) ? 1 : 0;
}

// ============================================================================
// Kernel 2: normalize rows -> bf16 (warp per row), labels, histogram, self-dot
// ============================================================================
__global__ void prep_kernel(const float* __restrict__ emb, const void* __restrict__ labels) {
    int warp = threadIdx.x >> 5, lane = threadIdx.x & 31;
    int row = blockIdx.x * 8 + warp;
    const float4* src = (const float4*)(emb + (size_t)row * DIMK);
    float4 v0 = __ldg(src + lane);
    float4 v1 = __ldg(src + lane + 32);
    float ss = v0.x * v0.x + v0.y * v0.y + v0.z * v0.z + v0.w * v0.w
             + v1.x * v1.x + v1.y * v1.y + v1.z * v1.z + v1.w * v1.w;
    #pragma unroll
    for (int o = 16; o; o >>= 1) ss += __shfl_xor_sync(0xffffffffu, ss, o);
    float inv = 1.0f / fmaxf(sqrtf(ss), 1e-12f);
    __nv_bfloat16 b[8];
    b[0] = __float2bfloat16(v0.x * inv); b[1] = __float2bfloat16(v0.y * inv);
    b[2] = __float2bfloat16(v0.z * inv); b[3] = __float2bfloat16(v0.w * inv);
    b[4] = __float2bfloat16(v1.x * inv); b[5] = __float2bfloat16(v1.y * inv);
    b[6] = __float2bfloat16(v1.z * inv); b[7] = __float2bfloat16(v1.w * inv);
    __nv_bfloat162* d2 = (__nv_bfloat162*)(g_en + (size_t)row * DIMK);
    d2[2 * lane + 0]  = __nv_bfloat162(b[0], b[1]);
    d2[2 * lane + 1]  = __nv_bfloat162(b[2], b[3]);
    d2[64 + 2 * lane] = __nv_bfloat162(b[4], b[5]);
    d2[65 + 2 * lane] = __nv_bfloat162(b[6], b[7]);
    // self-dot of the bf16-rounded row (the GEMM's diagonal value, to ~1e-7)
    float dd = 0.f;
    #pragma unroll
    for (int i = 0; i < 8; i++) {
        float f = __bfloat162float(b[i]);
        dd = fmaf(f, f, dd);
    }
    #pragma unroll
    for (int o = 16; o; o >>= 1) dd += __shfl_xor_sync(0xffffffffu, dd, o);
    if (lane == 0) {
        g_diag[row] = dd;
        int l = g_is64 ? (int)((const long long*)labels)[row] : ((const int*)labels)[row];
        g_lbl[row] = l;
        atomicAdd(&g_hist[l], 1);
    }
}

// ============================================================================
// Kernel 3: persistent fused bf16 mma.sync GEMM.
// 512 threads = 16 warps (4M x 4N, 32x32 warp tiles). NJOBS 128x128-tile jobs
// distributed over all SMs; jobs ordered row-major so each CTA's chunk spans
// <=2 row-tiles (segments). Epilogue of tile t-1 interleaved into tile t's
// MMA loop. No diagonal masking (finalize subtracts self-dot).
// ============================================================================
typedef float Acc[2][4][4];  // [mf][j][r]

template <bool HAS_PREV>
__device__ __forceinline__ void do_tile(
    int job, int segEnd, uint32_t sb, int tid, int lid, int warpN,
    uint32_t aAddr, uint32_t bOff,
    Acc& cur, Acc& prev,
    float* Sa, float* Pa, const int* myl,
    int* lpx, int* lpy)
{
    // B(job) arrival + all warps done with the buffer being prefetched into
    CP_WAIT0();
    __syncthreads();

    // prefetch B(job+1) within this segment
    if (job + 1 < segEnd) {
        load_tile(sb + SOFF_B0 + ((job + 1) & 1) * TILEB, ((job + 1) & 63) << 7, tid);
        CP_COMMIT();
    }

    #pragma unroll
    for (int mf = 0; mf < 2; mf++)
        #pragma unroll
        for (int j = 0; j < 4; j++)
            #pragma unroll
            for (int r = 0; r < 4; r++) cur[mf][j][r] = 0.f;

    uint32_t bAddr = sb + SOFF_B0 + (job & 1) * TILEB + bOff;

    #pragma unroll
    for (int ks = 0; ks < 16; ks++) {
        uint32_t a[2][4], b[2][4];
        ldsm4(a[0], aAddr + ks * 32);
        ldsm4(a[1], aAddr + 16 * ROWB + ks * 32);
        ldsm4(b[0], bAddr + ks * 32);
        ldsm4(b[1], bAddr + 16 * ROWB + ks * 32);
        #pragma unroll
        for (int mf = 0; mf < 2; mf++)
            #pragma unroll
            for (int jj = 0; jj < 2; jj++) {
                mma16816(cur[mf][2 * jj + 0], a[mf], &b[jj][0]);
                mma16816(cur[mf][2 * jj + 1], a[mf], &b[jj][2]);
            }
        if (HAS_PREV) {
            // interleaved epilogue: 2 values of previous tile's acc per ks step
            #pragma unroll
            for (int u = 0; u < 2; u++) {
                const int v = 2 * ks + u;
                const int mf = v >> 4, j = (v >> 2) & 3, rr = v & 3;
                const int hi = rr >> 1, lo = rr & 1;
                const int idx = mf * 2 + hi;
                float d = prev[mf][j][rr];
                Sa[idx] += ex2f(fmaf(d, K_EX2, -K_EX2));
                int lj = lo ? lpy[j] : lpx[j];
                if (lj == myl[idx]) Pa[idx] += d;
            }
        }
    }

    // stage this tile's column labels for its epilogue
    int cb = (job & 63) << 7;
    #pragma unroll
    for (int j = 0; j < 4; j++) {
        int2 lp = __ldg((const int2*)(g_lbl + cb + warpN * 32 + j * 8 + 2 * (lid & 3)));
        lpx[j] = lp.x;
        lpy[j] = lp.y;
    }
}

__device__ __forceinline__ void drain_acc(
    Acc& acc, const int* lpx, const int* lpy,
    float* Sa, float* Pa, const int* myl)
{
    #pragma unroll
    for (int v = 0; v < 32; v++) {
        const int mf = v >> 4, j = (v >> 2) & 3, rr = v & 3;
        const int hi = rr >> 1, lo = rr & 1;
        const int idx = mf * 2 + hi;
        float d = acc[mf][j][rr];
        Sa[idx] += ex2f(fmaf(d, K_EX2, -K_EX2));
        int lj = lo ? lpy[j] : lpx[j];
        if (lj == myl[idx]) Pa[idx] += d;
    }
}

__global__ void __launch_bounds__(512, 1) gemm_kernel(int ncta) {
    extern __shared__ char smem[];
    uint32_t sb = smem_u32(smem);
    float (*sS)[128] = (float(*)[128])(smem + SOFF_RED);
    float (*sP)[128] = (float(*)[128])(smem + SOFF_RED + 2048);
    int tid = threadIdx.x, wid = tid >> 5, lid = tid & 31;
    int warpM = wid & 3, warpN = wid >> 2;  // 4 x 4 warp grid, 32x32 warp tiles
    int bid = blockIdx.x;
    int start = (bid * NJOBS) / ncta;
    int end = ((bid + 1) * NJOBS) / ncta;

    // row-in-tile covered by each of this lane's 4 acc row-groups
    int rit[4];
    #pragma unroll
    for (int idx = 0; idx < 4; idx++)
        rit[idx] = warpM * 32 + (idx >> 1) * 16 + (idx & 1) * 8 + (lid >> 2);

    // ldmatrix per-lane base addresses
    uint32_t aAddr = sb + SOFF_A
        + (uint32_t)(warpM * 32 + (lid & 7) + ((lid >> 3) & 1) * 8) * ROWB
        + ((lid >> 4) & 1) * 16;
    uint32_t bOff =
        (uint32_t)(warpN * 32 + (lid & 7) + ((lid >> 4) & 1) * 8) * ROWB
        + ((lid >> 3) & 1) * 16;

    Acc acc0, acc1;
    int lpx[4], lpy[4];
    int job = start, seg = 0;

    while (job < end) {
        int r = job >> 6;
        int segEnd = min(end, (r + 1) << 6);
        int row_base = r << 7;
        int myl[4];
        #pragma unroll
        for (int idx = 0; idx < 4; idx++)
            myl[idx] = __ldg(&g_lbl[row_base + rit[idx]]);

        // segment prologue: A tile + first B tile as one cp.async group
        // (A buffer safe to overwrite: first segment, or post-store barrier)
        load_tile(sb + SOFF_A, row_base, tid);
        load_tile(sb + SOFF_B0 + (job & 1) * TILEB, (job & 63) << 7, tid);
        CP_COMMIT();

        float Sa[4] = {0.f, 0.f, 0.f, 0.f};
        float Pa[4] = {0.f, 0.f, 0.f, 0.f};
        int n = segEnd - job;

        do_tile<false>(job, segEnd, sb, tid, lid, warpN, aAddr, bOff,
                       acc0, acc1, Sa, Pa, myl, lpx, lpy);
        int k = 1;
        while (k + 2 <= n) {
            do_tile<true>(job + k, segEnd, sb, tid, lid, warpN, aAddr, bOff,
                          acc1, acc0, Sa, Pa, myl, lpx, lpy);
            do_tile<true>(job + k + 1, segEnd, sb, tid, lid, warpN, aAddr, bOff,
                          acc0, acc1, Sa, Pa, myl, lpx, lpy);
            k += 2;
        }
        if (k < n) {
            do_tile<true>(job + k, segEnd, sb, tid, lid, warpN, aAddr, bOff,
                          acc1, acc0, Sa, Pa, myl, lpx, lpy);
            drain_acc(acc1, lpx, lpy, Sa, Pa, myl);
        } else {
            drain_acc(acc0, lpx, lpy, Sa, Pa, myl);
        }
        job = segEnd;

        // ---- segment store: quad reduce, cross-warpN reduce in smem ----
        #pragma unroll
        for (int idx = 0; idx < 4; idx++) {
            float s = Sa[idx], p = Pa[idx];
            s += __shfl_xor_sync(0xffffffffu, s, 1);
            s += __shfl_xor_sync(0xffffffffu, s, 2);
            p += __shfl_xor_sync(0xffffffffu, p, 1);
            p += __shfl_xor_sync(0xffffffffu, p, 2);
            if ((lid & 3) == 0) {
                sS[warpN][rit[idx]] = s;
                sP[warpN][rit[idx]] = p;
            }
        }
        __syncthreads();
        if (tid < 128) {
            g_S2[bid][seg][tid] = sS[0][tid] + sS[1][tid] + sS[2][tid] + sS[3][tid];
            g_P2[bid][seg][tid] = sP[0][tid] + sP[1][tid] + sP[2][tid] + sP[3][tid];
        }
        if (tid == 0) g_seg_r[bid][seg] = r;
        __syncthreads();  // also protects A/B buffers before next segment's loads
        seg++;
    }
}

// ============================================================================
// Kernel 4: final reduction -> scalar mean loss. 8 blocks x 1024 threads,
// one row per thread; deterministic candidate-CTA scan + last-block combine.
// ============================================================================
__global__ void finalize_kernel(float* __restrict__ out, int ncta) {
    int tid = threadIdx.x;
    int row = blockIdx.x * 1024 + tid;  // one row per thread
    int r = row >> 7, rit = row & 127;
    int g0 = r << 6, g1 = g0 + 63;
    int jlo = (g0 * ncta) >> 12; jlo = (jlo > 0) ? jlo - 1 : 0;
    int jhi = ((g1 * ncta) >> 12) + 1; if (jhi > ncta - 1) jhi = ncta - 1;

    float S = 0.f, P = 0.f;
    for (int j = jlo; j <= jhi; j++) {
        #pragma unroll
        for (int seg = 0; seg < 4; seg++) {
            if (g_seg_r[j][seg] == r) {
                S += g_S2[j][seg][rit];
                P += g_P2[j][seg][rit];
            }
        }
    }
    P -= g_diag[row];  // exclude self from positives
    int cnt = g_hist[g_lbl[row]] - 1;
    float acc = (cnt > 0) ? (TEMP_INV + __logf(S) - (P * TEMP_INV) / (float)cnt) : 0.f;

    #pragma unroll
    for (int o = 16; o; o >>= 1) acc += __shfl_xor_sync(0xffffffffu, acc, o);
    __shared__ float ws[32];
    if ((tid & 31) == 0) ws[tid >> 5] = acc;
    __syncthreads();
    if (tid < 32) {
        float v = ws[tid];
        #pragma unroll
        for (int o = 16; o; o >>= 1) v += __shfl_xor_sync(0xffffffffu, v, o);
        if (tid == 0) {
            g_pb[blockIdx.x] = v;
            __threadfence();
            int prev = atomicAdd(&g_done, 1);
            if (prev == 7) {  // last block: fixed-order combine (deterministic)
                float tot = 0.f;
                #pragma unroll
                for (int b = 0; b < 8; b++) tot += ((volatile float*)g_pb)[b];
                out[0] = tot / (float)NROWS;
            }
        }
    }
}

// ============================================================================
// Launch
// ============================================================================
extern "C" void kernel_launch(void* const* d_in, const int* in_sizes, int n_in,
                              void* d_out, int out_size) {
    const float* emb;
    const void* lab;
    if (in_sizes[0] == NROWS * DIMK) {
        emb = (const float*)d_in[0];
        lab = d_in[1];
    } else {
        emb = (const float*)d_in[1];
        lab = d_in[0];
    }

    int dev = 0;
    cudaGetDevice(&dev);
    int ncta = 0;
    cudaDeviceGetAttribute(&ncta, cudaDevAttrMultiProcessorCount, dev);
    if (ncta < 16 || ncta > MAXCTA) ncta = 128;

    cudaFuncSetAttribute(gemm_kernel, cudaFuncAttributeMaxDynamicSharedMemorySize, SMEM_TOTAL);

    init_kernel<<<1, 1024>>>((const int*)lab);
    prep_kernel<<<NROWS / 8, 256>>>(emb, lab);
    gemm_kernel<<<ncta, 512, SMEM_TOTAL>>>(ncta);
    finalize_kernel<<<8, 1024>>>((float*)d_out, ncta);
}

// round 7
// speedup vs baseline: 1.7399x; 1.2312x over previous
#include <cuda_runtime.h>
#include <cuda_bf16.h>
#include <stdint.h>

// ============================================================================
// Problem constants
// ============================================================================
#define NROWS 8192
#define DIMK  256
#define NLBL  1024
#define NRT   64                       // 128-row tiles
#define NJOBS 2080                     // upper-triangular tiles: 64*65/2
#define MAXSEG 8
#define MAXCTA 256
#define TEMP_INV 14.285714285714286f   // 1/0.07
// exp((d-1)/T) = 2^(d*K - K), K = (1/T)*log2(e)
#define K_EX2 20.609929191666664f

// ============================================================================
// Device scratch (no allocation allowed; zero-initialized at load)
// ============================================================================
__device__ __align__(128) __nv_bfloat16 g_en[NROWS * DIMK];  // normalized rows, bf16
__device__ int   g_lbl[NROWS];
__device__ int   g_hist[NLBL];
__device__ int   g_is64;
__device__ float g_diag[NROWS];                 // self-dot of bf16 row (fp32)
__device__ float g_colS[NJOBS][128];            // per-job column exp-sums
__device__ float g_colP[NJOBS][128];            // per-job column positive-sums
__device__ float g_S2[MAXCTA][MAXSEG][128];     // per-(CTA, segment) row exp-sum partials
__device__ float g_P2[MAXCTA][MAXSEG][128];     // per-(CTA, segment) row positive partials
__device__ int   g_seg_r[MAXCTA][MAXSEG];       // rtile id of each segment
__device__ float g_pb[32];                      // per-block partial losses
__device__ int   g_done;                        // finalize completion counter

// ============================================================================
// PTX helpers (baseline sm_80+ only — target is compute_103 WITHOUT 'a')
// ============================================================================
__device__ __forceinline__ uint32_t smem_u32(const void* p) {
    uint32_t a;
    asm("{ .reg .u64 t; cvta.to.shared.u64 t, %1; cvt.u32.u64 %0, t; }" : "=r"(a) : "l"(p));
    return a;
}

__device__ __forceinline__ void cp16(uint32_t dst, const void* src) {
    asm volatile("cp.async.cg.shared.global [%0], [%1], 16;" :: "r"(dst), "l"(src));
}
#define CP_COMMIT() asm volatile("cp.async.commit_group;" ::: "memory")
#define CP_WAIT0()  asm volatile("cp.async.wait_group 0;" ::: "memory")

__device__ __forceinline__ void ldsm4(uint32_t* r, uint32_t addr) {
    asm volatile("ldmatrix.sync.aligned.m8n8.x4.shared.b16 {%0,%1,%2,%3}, [%4];"
        : "=r"(r[0]), "=r"(r[1]), "=r"(r[2]), "=r"(r[3]) : "r"(addr));
}

__device__ __forceinline__ void mma16816(float* d, const uint32_t* a, const uint32_t* b) {
    asm volatile(
        "mma.sync.aligned.m16n8k16.row.col.f32.bf16.bf16.f32 "
        "{%0,%1,%2,%3}, {%4,%5,%6,%7}, {%8,%9}, {%0,%1,%2,%3};"
        : "+f"(d[0]), "+f"(d[1]), "+f"(d[2]), "+f"(d[3])
        : "r"(a[0]), "r"(a[1]), "r"(a[2]), "r"(a[3]), "r"(b[0]), "r"(b[1]));
}

__device__ __forceinline__ float ex2f(float x) {
    float e;
    asm("ex2.approx.f32 %0, %1;" : "=f"(e) : "f"(x));
    return e;
}

// triangular row-major job index: row r starts at jstart(r); job(r,c) = jstart(r) + c - r
__host__ __device__ __forceinline__ int jstart(int r) { return (r * (129 - r)) >> 1; }

// ============================================================================
// SMEM layout (padded K-major tiles: 128 rows x 264 bf16 -> 528 B row stride)
// ============================================================================
#define ROWB   528
#define TILEB  (128 * ROWB)                 // 67584
#define SOFF_A   0
#define SOFF_B0  TILEB
#define SOFF_ROW (3 * TILEB)                // sS[4][128], sP[4][128]  (4 KB)
#define SOFF_COL (3 * TILEB + 4096)         // sCS[2][4][128], sCP[2][4][128] (8 KB)
#define SMEM_TOTAL (3 * TILEB + 4096 + 8192)  // 215040

// Fill one 128-row x 256-col bf16 tile via cp.async. 512 threads, 4096 chunks.
__device__ __forceinline__ void load_tile(uint32_t dst_base, int grow_base, int tid) {
    #pragma unroll
    for (int i = 0; i < 8; i++) {
        int c = tid + i * 512;     // 0..4095
        int r = c >> 5;            // row
        int q = c & 31;            // 16B chunk
        cp16(dst_base + r * ROWB + q * 16,
             (const void*)(g_en + (size_t)(grow_base + r) * DIMK + q * 8));
    }
}

// ============================================================================
// Kernel 1: zero histogram, seg_r, counters; detect labels dtype
// ============================================================================
__global__ void init_kernel(const int* lab32) {
    int tid = threadIdx.x;  // 1024
    if (tid < NLBL) g_hist[tid] = 0;
    if (tid < MAXCTA * MAXSEG) ((int*)g_seg_r)[tid] = -1;
    if (tid + 1024 < MAXCTA * MAXSEG) ((int*)g_seg_r)[tid + 1024] = -1;
    if (tid == 0) g_done = 0;
    __shared__ int any;
    if (tid == 0) any = 0;
    __syncthreads();
    for (int i = tid; i < 4096; i += 1024)
        if (lab32[2 * i + 1] != 0) any = 1;  // benign race
    __syncthreads();
    if (tid == 0) g_is64 = (any == 0) ? 1 : 0;
}

// ============================================================================
// Kernel 2: normalize rows -> bf16 (warp per row), labels, histogram, self-dot
// ============================================================================
__global__ void prep_kernel(const float* __restrict__ emb, const void* __restrict__ labels) {
    int warp = threadIdx.x >> 5, lane = threadIdx.x & 31;
    int row = blockIdx.x * 8 + warp;
    const float4* src = (const float4*)(emb + (size_t)row * DIMK);
    float4 v0 = __ldg(src + lane);
    float4 v1 = __ldg(src + lane + 32);
    float ss = v0.x * v0.x + v0.y * v0.y + v0.z * v0.z + v0.w * v0.w
             + v1.x * v1.x + v1.y * v1.y + v1.z * v1.z + v1.w * v1.w;
    #pragma unroll
    for (int o = 16; o; o >>= 1) ss += __shfl_xor_sync(0xffffffffu, ss, o);
    float inv = 1.0f / fmaxf(sqrtf(ss), 1e-12f);
    __nv_bfloat16 b[8];
    b[0] = __float2bfloat16(v0.x * inv); b[1] = __float2bfloat16(v0.y * inv);
    b[2] = __float2bfloat16(v0.z * inv); b[3] = __float2bfloat16(v0.w * inv);
    b[4] = __float2bfloat16(v1.x * inv); b[5] = __float2bfloat16(v1.y * inv);
    b[6] = __float2bfloat16(v1.z * inv); b[7] = __float2bfloat16(v1.w * inv);
    __nv_bfloat162* d2 = (__nv_bfloat162*)(g_en + (size_t)row * DIMK);
    d2[2 * lane + 0]  = __nv_bfloat162(b[0], b[1]);
    d2[2 * lane + 1]  = __nv_bfloat162(b[2], b[3]);
    d2[64 + 2 * lane] = __nv_bfloat162(b[4], b[5]);
    d2[65 + 2 * lane] = __nv_bfloat162(b[6], b[7]);
    float dd = 0.f;
    #pragma unroll
    for (int i = 0; i < 8; i++) {
        float f = __bfloat162float(b[i]);
        dd = fmaf(f, f, dd);
    }
    #pragma unroll
    for (int o = 16; o; o >>= 1) dd += __shfl_xor_sync(0xffffffffu, dd, o);
    if (lane == 0) {
        g_diag[row] = dd;
        int l = g_is64 ? (int)((const long long*)labels)[row] : ((const int*)labels)[row];
        g_lbl[row] = l;
        atomicAdd(&g_hist[l], 1);
    }
}

// ============================================================================
// Kernel 3: persistent symmetric fused GEMM (upper-triangular tiles only).
// 512 threads = 16 warps (4M x 4N, 32x32 warp tiles). For each off-diagonal
// tile, one exp feeds BOTH the row accumulators (block r) and the column
// accumulators (block c, stored per-job). Diagonal tiles: rows only.
// ============================================================================
typedef float Acc[2][4][4];  // [mf][j][r]

struct EpiState {
    float Sa[4], Pa[4];   // row accumulators
    float cS[8], cP[8];   // column accumulators (current epi tile)
    int lpx[4], lpy[4];   // staged column labels
    int myl[4];           // row labels
};

__device__ __forceinline__ void col_flush(
    char* smem, EpiState& es, int par, int warpM, int warpN, int lid)
{
    float* sCS = (float*)(smem + SOFF_COL) + par * 512;
    float* sCP = (float*)(smem + SOFF_COL + 4096) + par * 512;
    #pragma unroll
    for (int cj = 0; cj < 8; cj++) {
        float s = es.cS[cj], p = es.cP[cj];
        s += __shfl_xor_sync(0xffffffffu, s, 4);
        s += __shfl_xor_sync(0xffffffffu, s, 8);
        s += __shfl_xor_sync(0xffffffffu, s, 16);
        p += __shfl_xor_sync(0xffffffffu, p, 4);
        p += __shfl_xor_sync(0xffffffffu, p, 8);
        p += __shfl_xor_sync(0xffffffffu, p, 16);
        if (lid < 4) {
            int col = warpN * 32 + (cj >> 1) * 8 + 2 * lid + (cj & 1);
            sCS[warpM * 128 + col] = s;
            sCP[warpM * 128 + col] = p;
        }
        es.cS[cj] = 0.f;
        es.cP[cj] = 0.f;
    }
}

__device__ __forceinline__ void pend_store(char* smem, int pend, int tid) {
    if (pend >= 0 && tid < 128) {
        int par = pend & 1;
        float* sCS = (float*)(smem + SOFF_COL) + par * 512;
        float* sCP = (float*)(smem + SOFF_COL + 4096) + par * 512;
        g_colS[pend][tid] = sCS[tid] + sCS[128 + tid] + sCS[256 + tid] + sCS[384 + tid];
        g_colP[pend][tid] = sCP[tid] + sCP[128 + tid] + sCP[256 + tid] + sCP[384 + tid];
    }
}

template <bool HAS_PREV>
__device__ __forceinline__ void do_tile(
    int jc, int cb_cur, int segEnd, char* smem, uint32_t sb,
    int tid, int lid, int warpM, int warpN,
    uint32_t aAddr, uint32_t bOff,
    Acc& cur, Acc& prev, EpiState& es, int& pend, bool prev_offd)
{
    CP_WAIT0();
    __syncthreads();

    // prefetch next B tile within this segment
    if (jc + 1 < segEnd) {
        load_tile(sb + SOFF_B0 + ((jc + 1) & 1) * TILEB, cb_cur + 128, tid);
        CP_COMMIT();
    }
    // store previously-flushed column sums (smem buffer par(pend), safe post-sync)
    if (HAS_PREV) pend_store(smem, pend, tid);

    #pragma unroll
    for (int mf = 0; mf < 2; mf++)
        #pragma unroll
        for (int j = 0; j < 4; j++)
            #pragma unroll
            for (int rr = 0; rr < 4; rr++) cur[mf][j][rr] = 0.f;

    uint32_t bAddr = sb + SOFF_B0 + (jc & 1) * TILEB + bOff;

    #pragma unroll
    for (int ks = 0; ks < 16; ks++) {
        uint32_t a[2][4], b[2][4];
        ldsm4(a[0], aAddr + ks * 32);
        ldsm4(a[1], aAddr + 16 * ROWB + ks * 32);
        ldsm4(b[0], bAddr + ks * 32);
        ldsm4(b[1], bAddr + 16 * ROWB + ks * 32);
        #pragma unroll
        for (int mf = 0; mf < 2; mf++)
            #pragma unroll
            for (int jj = 0; jj < 2; jj++) {
                mma16816(cur[mf][2 * jj + 0], a[mf], &b[jj][0]);
                mma16816(cur[mf][2 * jj + 1], a[mf], &b[jj][2]);
            }
        if (HAS_PREV) {
            // interleaved epilogue: 2 values of previous tile's acc per ks step
            #pragma unroll
            for (int u = 0; u < 2; u++) {
                const int v = 2 * ks + u;
                const int mf = v >> 4, j = (v >> 2) & 3, rr = v & 3;
                const int hi = rr >> 1, lo = rr & 1;
                const int idx = mf * 2 + hi;
                const int cj = j * 2 + lo;
                float d = prev[mf][j][rr];
                float e = ex2f(fmaf(d, K_EX2, -K_EX2));
                es.Sa[idx] += e;
                int lj = lo ? es.lpy[j] : es.lpx[j];
                bool m = (lj == es.myl[idx]);
                if (m) es.Pa[idx] += d;
                if (prev_offd) {
                    es.cS[cj] += e;
                    if (m) es.cP[cj] += d;
                }
            }
        }
    }

    if (HAS_PREV) {
        if (prev_offd) {
            col_flush(smem, es, (jc - 1) & 1, warpM, warpN, lid);
            pend = jc - 1;
        } else {
            pend = -1;
        }
    }

    // stage this tile's column labels for its epilogue
    #pragma unroll
    for (int j = 0; j < 4; j++) {
        int2 lp = __ldg((const int2*)(g_lbl + cb_cur + warpN * 32 + j * 8 + 2 * (lid & 3)));
        es.lpx[j] = lp.x;
        es.lpy[j] = lp.y;
    }
}

__device__ __forceinline__ void drain_acc(Acc& acc, EpiState& es, bool offd) {
    #pragma unroll
    for (int v = 0; v < 32; v++) {
        const int mf = v >> 4, j = (v >> 2) & 3, rr = v & 3;
        const int hi = rr >> 1, lo = rr & 1;
        const int idx = mf * 2 + hi;
        const int cj = j * 2 + lo;
        float d = acc[mf][j][rr];
        float e = ex2f(fmaf(d, K_EX2, -K_EX2));
        es.Sa[idx] += e;
        int lj = lo ? es.lpy[j] : es.lpx[j];
        bool m = (lj == es.myl[idx]);
        if (m) es.Pa[idx] += d;
        if (offd) {
            es.cS[cj] += e;
            if (m) es.cP[cj] += d;
        }
    }
}

__global__ void __launch_bounds__(512, 1) gemm_kernel(int ncta) {
    extern __shared__ char smem[];
    uint32_t sb = smem_u32(smem);
    float (*sS)[128] = (float(*)[128])(smem + SOFF_ROW);
    float (*sP)[128] = (float(*)[128])(smem + SOFF_ROW + 2048);
    int tid = threadIdx.x, wid = tid >> 5, lid = tid & 31;
    int warpM = wid & 3, warpN = wid >> 2;  // 4 x 4 warp grid, 32x32 warp tiles
    int bid = blockIdx.x;
    int start = (bid * NJOBS) / ncta;
    int end = ((bid + 1) * NJOBS) / ncta;

    // row-in-tile covered by each of this lane's 4 acc row-groups
    int rit[4];
    #pragma unroll
    for (int idx = 0; idx < 4; idx++)
        rit[idx] = warpM * 32 + (idx >> 1) * 16 + (idx & 1) * 8 + (lid >> 2);

    // ldmatrix per-lane base addresses
    uint32_t aAddr = sb + SOFF_A
        + (uint32_t)(warpM * 32 + (lid & 7) + ((lid >> 3) & 1) * 8) * ROWB
        + ((lid >> 4) & 1) * 16;
    uint32_t bOff =
        (uint32_t)(warpN * 32 + (lid & 7) + ((lid >> 4) & 1) * 8) * ROWB
        + ((lid >> 3) & 1) * 16;

    Acc acc0, acc1;
    EpiState es;
    #pragma unroll
    for (int i = 0; i < 8; i++) { es.cS[i] = 0.f; es.cP[i] = 0.f; }

    int job = start, seg = 0, r = 0, pend = -1;

    while (job < end) {
        while (jstart(r + 1) <= job) r++;
        int jsr = jstart(r);
        int segEnd = min(end, jstart(r + 1));
        int row_base = r << 7;
        int c0 = r + (job - jsr);
        int cb0 = c0 << 7;
        #pragma unroll
        for (int idx = 0; idx < 4; idx++)
            es.myl[idx] = __ldg(&g_lbl[row_base + rit[idx]]);
        #pragma unroll
        for (int idx = 0; idx < 4; idx++) { es.Sa[idx] = 0.f; es.Pa[idx] = 0.f; }

        // segment prologue: A tile + first B tile as one cp.async group
        load_tile(sb + SOFF_A, row_base, tid);
        load_tile(sb + SOFF_B0 + (job & 1) * TILEB, cb0, tid);
        CP_COMMIT();

        int n = segEnd - job;
        do_tile<false>(job, cb0, segEnd, smem, sb, tid, lid, warpM, warpN,
                       aAddr, bOff, acc0, acc1, es, pend, false);
        int k = 1;
        while (k + 2 <= n) {
            do_tile<true>(job + k, cb0 + (k << 7), segEnd, smem, sb, tid, lid, warpM, warpN,
                          aAddr, bOff, acc1, acc0, es, pend, (job + k - 1) != jsr);
            do_tile<true>(job + k + 1, cb0 + ((k + 1) << 7), segEnd, smem, sb, tid, lid, warpM, warpN,
                          aAddr, bOff, acc0, acc1, es, pend, true);
            k += 2;
        }
        bool offd_last = (segEnd - 1) != jsr;
        if (k < n) {
            do_tile<true>(job + k, cb0 + (k << 7), segEnd, smem, sb, tid, lid, warpM, warpN,
                          aAddr, bOff, acc1, acc0, es, pend, (job + k - 1) != jsr);
            drain_acc(acc1, es, offd_last);
        } else {
            drain_acc(acc0, es, offd_last);
        }

        // flush last tile's columns into the other-parity smem buffer
        int parL = (segEnd - 1) & 1;
        if (offd_last) col_flush(smem, es, parL, warpM, warpN, lid);

        // row partials: quad reduce -> smem
        #pragma unroll
        for (int idx = 0; idx < 4; idx++) {
            float s = es.Sa[idx], p = es.Pa[idx];
            s += __shfl_xor_sync(0xffffffffu, s, 1);
            s += __shfl_xor_sync(0xffffffffu, s, 2);
            p += __shfl_xor_sync(0xffffffffu, p, 1);
            p += __shfl_xor_sync(0xffffffffu, p, 2);
            if ((lid & 3) == 0) {
                sS[warpN][rit[idx]] = s;
                sP[warpN][rit[idx]] = p;
            }
        }
        __syncthreads();
        if (tid < 128) {
            // pending (second-to-last) and last column stores + row partial store
            if (pend >= 0) {
                float* sCS = (float*)(smem + SOFF_COL) + (pend & 1) * 512;
                float* sCP = (float*)(smem + SOFF_COL + 4096) + (pend & 1) * 512;
                g_colS[pend][tid] = sCS[tid] + sCS[128 + tid] + sCS[256 + tid] + sCS[384 + tid];
                g_colP[pend][tid] = sCP[tid] + sCP[128 + tid] + sCP[256 + tid] + sCP[384 + tid];
            }
            if (offd_last) {
                float* sCS = (float*)(smem + SOFF_COL) + parL * 512;
                float* sCP = (float*)(smem + SOFF_COL + 4096) + parL * 512;
                g_colS[segEnd - 1][tid] = sCS[tid] + sCS[128 + tid] + sCS[256 + tid] + sCS[384 + tid];
                g_colP[segEnd - 1][tid] = sCP[tid] + sCP[128 + tid] + sCP[256 + tid] + sCP[384 + tid];
            }
            g_S2[bid][seg][tid] = sS[0][tid] + sS[1][tid] + sS[2][tid] + sS[3][tid];
            g_P2[bid][seg][tid] = sP[0][tid] + sP[1][tid] + sP[2][tid] + sP[3][tid];
        }
        if (tid == 0) g_seg_r[bid][seg] = r;
        __syncthreads();  // protects smem buffers before next segment
        pend = -1;
        job = segEnd;
        seg++;
    }
}

// ============================================================================
// Kernel 4: final reduction -> scalar mean loss. 32 blocks x 256 threads,
// one row per thread; col-slot gather + candidate-CTA row scan; deterministic.
// ============================================================================
__global__ void finalize_kernel(float* __restrict__ out, int ncta) {
    int tid = threadIdx.x;
    int row = blockIdx.x * 256 + tid;  // one row per thread
    int b = row >> 7, rit = row & 127;

    float S = 0.f, P = 0.f;
    // column contributions from tiles (r2, b), r2 < b
    for (int r2 = 0; r2 < b; r2++) {
        int j = jstart(r2) + (b - r2);
        S += g_colS[j][rit];
        P += g_colP[j][rit];
    }
    // row contributions from segments with r == b
    int j0 = jstart(b), j1 = jstart(b + 1) - 1;
    int jlo = (int)(((long long)j0 * ncta) / NJOBS) - 2; if (jlo < 0) jlo = 0;
    int jhi = (int)(((long long)j1 * ncta) / NJOBS) + 2; if (jhi > ncta - 1) jhi = ncta - 1;
    for (int q = jlo; q <= jhi; q++) {
        #pragma unroll
        for (int seg = 0; seg < MAXSEG; seg++) {
            if (g_seg_r[q][seg] == b) {
                S += g_S2[q][seg][rit];
                P += g_P2[q][seg][rit];
            }
        }
    }
    P -= g_diag[row];  // exclude self from positives
    int cnt = g_hist[g_lbl[row]] - 1;
    float acc = (cnt > 0) ? (TEMP_INV + __logf(S) - (P * TEMP_INV) / (float)cnt) : 0.f;

    #pragma unroll
    for (int o = 16; o; o >>= 1) acc += __shfl_xor_sync(0xffffffffu, acc, o);
    __shared__ float ws[8];
    if ((tid & 31) == 0) ws[tid >> 5] = acc;
    __syncthreads();
    if (tid == 0) {
        float v = ws[0] + ws[1] + ws[2] + ws[3] + ws[4] + ws[5] + ws[6] + ws[7];
        g_pb[blockIdx.x] = v;
        __threadfence();
        int prev = atomicAdd(&g_done, 1);
        if (prev == 31) {  // last block: fixed-order combine (deterministic)
            float tot = 0.f;
            #pragma unroll
            for (int bb = 0; bb < 32; bb++) tot += ((volatile float*)g_pb)[bb];
            out[0] = tot / (float)NROWS;
        }
    }
}

// ============================================================================
// Launch
// ============================================================================
extern "C" void kernel_launch(void* const* d_in, const int* in_sizes, int n_in,
                              void* d_out, int out_size) {
    const float* emb;
    const void* lab;
    if (in_sizes[0] == NROWS * DIMK) {
        emb = (const float*)d_in[0];
        lab = d_in[1];
    } else {
        emb = (const float*)d_in[1];
        lab = d_in[0];
    }

    int dev = 0;
    cudaGetDevice(&dev);
    int ncta = 0;
    cudaDeviceGetAttribute(&ncta, cudaDevAttrMultiProcessorCount, dev);
    if (ncta < 100 || ncta > MAXCTA) ncta = 128;

    cudaFuncSetAttribute(gemm_kernel, cudaFuncAttributeMaxDynamicSharedMemorySize, SMEM_TOTAL);

    init_kernel<<<1, 1024>>>((const int*)lab);
    prep_kernel<<<NROWS / 8, 256>>>(emb, lab);
    gemm_kernel<<<ncta, 512, SMEM_TOTAL>>>(ncta);
    finalize_kernel<<<32, 256>>>((float*)d_out, ncta);
}